// round 1
// baseline (speedup 1.0000x reference)
#include <cuda_runtime.h>
#include <cuda_bf16.h>
#include <cstdint>

// Problem constants
#define Bn   256
#define Nn   197
#define Cc   768
#define Hh   12
#define Dd   64
#define GRID3 14

// Scratch (device globals: allocation-free, graph-capturable)
__device__ float g_qkv[(size_t)Bn * Nn * 3 * Cc];   // (B,N,3C) row-major
__device__ float g_att[(size_t)Bn * Nn * Cc];       // (B,N,C)  attention out (+conv)

// ---------------------------------------------------------------------------
// Classic 128x128x8 register-blocked SGEMM, C = A(MxK) * B(KxN) + bias(N)
// Assumes M%128==0, N%128==0, K%8==0 (true for all calls here).
// ---------------------------------------------------------------------------
__global__ __launch_bounds__(256) void sgemm128(
    const float* __restrict__ A, const float* __restrict__ B,
    const float* __restrict__ bias, float* __restrict__ C,
    int M, int N, int K)
{
    __shared__ float As[8][128];
    __shared__ float Bs[8][128];

    const int bx = blockIdx.x;   // N tile
    const int by = blockIdx.y;   // M tile
    const int tid = threadIdx.x;
    const int trow = tid >> 4;        // 0..15
    const int tcol = tid & 15;        // 0..15

    const int aRow = tid >> 1;        // 0..127
    const int aCol = (tid & 1) * 4;   // 0 or 4
    const int bRow = tid >> 5;        // 0..7
    const int bCol = (tid & 31) * 4;  // 0..124

    const float* Aptr = A + (size_t)(by * 128 + aRow) * K + aCol;
    const float* Bptr = B + (size_t)bRow * N + bx * 128 + bCol;

    float acc[8][8];
#pragma unroll
    for (int i = 0; i < 8; i++)
#pragma unroll
        for (int j = 0; j < 8; j++) acc[i][j] = 0.f;

    for (int k0 = 0; k0 < K; k0 += 8) {
        float4 a4 = *(const float4*)Aptr; Aptr += 8;
        float4 b4 = *(const float4*)Bptr; Bptr += (size_t)8 * N;

        As[aCol + 0][aRow] = a4.x;
        As[aCol + 1][aRow] = a4.y;
        As[aCol + 2][aRow] = a4.z;
        As[aCol + 3][aRow] = a4.w;
        *(float4*)&Bs[bRow][bCol] = b4;
        __syncthreads();

#pragma unroll
        for (int kk = 0; kk < 8; ++kk) {
            float ar[8], br[8];
#pragma unroll
            for (int i = 0; i < 8; i++) ar[i] = As[kk][trow * 8 + i];
#pragma unroll
            for (int j = 0; j < 8; j++) br[j] = Bs[kk][tcol * 8 + j];
#pragma unroll
            for (int i = 0; i < 8; i++)
#pragma unroll
                for (int j = 0; j < 8; j++)
                    acc[i][j] += ar[i] * br[j];
        }
        __syncthreads();
    }

    const float* brow = bias + bx * 128 + tcol * 8;
    float bv[8];
#pragma unroll
    for (int j = 0; j < 8; j++) bv[j] = brow[j];

#pragma unroll
    for (int i = 0; i < 8; i++) {
        int row = by * 128 + trow * 8 + i;
        float* Crow = C + (size_t)row * N + bx * 128 + tcol * 8;
        float4 c0, c1;
        c0.x = acc[i][0] + bv[0]; c0.y = acc[i][1] + bv[1];
        c0.z = acc[i][2] + bv[2]; c0.w = acc[i][3] + bv[3];
        c1.x = acc[i][4] + bv[4]; c1.y = acc[i][5] + bv[5];
        c1.z = acc[i][6] + bv[6]; c1.w = acc[i][7] + bv[7];
        *(float4*)(Crow)     = c0;
        *(float4*)(Crow + 4) = c1;
    }
}

// ---------------------------------------------------------------------------
// Attention: one CTA per (b,h). K,V tiles resident in smem (stride-65 pad).
// qkv layout: row (b*197+n), col t*768 + h*64 + d   (t: 0=q,1=k,2=v)
// Writes att[b, n, h*64+d].
// ---------------------------------------------------------------------------
#define KV_STRIDE 65
#define SMEM_ATTN ((2 * Nn * KV_STRIDE + 8 * 200 + 8 * 64) * (int)sizeof(float))

__global__ __launch_bounds__(256) void attn_kernel(
    const float* __restrict__ qkv, float* __restrict__ att)
{
    extern __shared__ float smem[];
    float* Ks = smem;                       // 197*65
    float* Vs = Ks + Nn * KV_STRIDE;        // 197*65
    float* pb = Vs + Nn * KV_STRIDE;        // 8*200
    float* qb = pb + 8 * 200;               // 8*64

    const int bh = blockIdx.x;
    const int b = bh / Hh, h = bh % Hh;
    const int tid = threadIdx.x, lane = tid & 31, w = tid >> 5;
    const float scale = 0.125f;             // 64^-0.5

    const float* base = qkv + (size_t)b * Nn * (3 * Cc) + h * Dd;

    // cooperative load of K and V into smem
    for (int idx = tid; idx < Nn * Dd; idx += 256) {
        int j = idx >> 6, d = idx & 63;
        size_t roff = (size_t)j * (3 * Cc);
        Ks[j * KV_STRIDE + d] = base[roff + Cc + d];
        Vs[j * KV_STRIDE + d] = base[roff + 2 * Cc + d];
    }
    __syncthreads();

    float* pw = pb + w * 200;
    float* qw = qb + w * 64;

    for (int row = w; row < Nn; row += 8) {
        // stage this row's q
        qw[lane]      = base[(size_t)row * (3 * Cc) + lane];
        qw[lane + 32] = base[(size_t)row * (3 * Cc) + lane + 32];
        __syncwarp();

        float s[7];
        float mx = -1e30f;
#pragma unroll
        for (int jj = 0; jj < 7; ++jj) {
            int j = lane + jj * 32;
            float a = -1e30f;
            if (j < Nn) {
                const float* kp = Ks + j * KV_STRIDE;
                float acc = 0.f;
#pragma unroll
                for (int d = 0; d < 64; ++d) acc += qw[d] * kp[d];
                a = acc * scale;
            }
            s[jj] = a;
            mx = fmaxf(mx, a);
        }
#pragma unroll
        for (int o = 16; o; o >>= 1) mx = fmaxf(mx, __shfl_xor_sync(~0u, mx, o));

        float sum = 0.f;
#pragma unroll
        for (int jj = 0; jj < 7; ++jj) { s[jj] = __expf(s[jj] - mx); sum += s[jj]; }
#pragma unroll
        for (int o = 16; o; o >>= 1) sum += __shfl_xor_sync(~0u, sum, o);
        float inv = 1.f / sum;
#pragma unroll
        for (int jj = 0; jj < 7; ++jj) {
            int j = lane + jj * 32;
            if (j < Nn) pw[j] = s[jj] * inv;
        }
        __syncwarp();

        float a0 = 0.f, a1 = 0.f;
        for (int j = 0; j < Nn; ++j) {
            float p = pw[j];
            a0 += p * Vs[j * KV_STRIDE + lane];
            a1 += p * Vs[j * KV_STRIDE + lane + 32];
        }
        float* o = att + ((size_t)(b * Nn + row)) * Cc + h * Dd;
        o[lane]      = a0;
        o[lane + 32] = a1;
        __syncwarp();
    }
}

// ---------------------------------------------------------------------------
// Depthwise 3x3 conv on V (rows 1..196 of each sequence), accumulate into att.
// ---------------------------------------------------------------------------
__global__ __launch_bounds__(256) void dwconv_kernel(
    const float* __restrict__ qkv, const float* __restrict__ wgt,
    const float* __restrict__ bias, float* __restrict__ att)
{
    size_t idx = (size_t)blockIdx.x * 256 + threadIdx.x;
    const size_t total = (size_t)Bn * (GRID3 * GRID3) * Cc;
    if (idx >= total) return;

    int c = idx % Cc;
    size_t t = idx / Cc;
    int x = t % GRID3; t /= GRID3;
    int y = t % GRID3;
    int b = t / GRID3;

    const float* vbase = qkv + (size_t)b * Nn * (3 * Cc) + 2 * Cc + c;
    float acc = bias[c];
#pragma unroll
    for (int dy = -1; dy <= 1; ++dy) {
        int yy = y + dy;
        if (yy < 0 || yy >= GRID3) continue;
#pragma unroll
        for (int dx = -1; dx <= 1; ++dx) {
            int xx = x + dx;
            if (xx < 0 || xx >= GRID3) continue;
            int pix = yy * GRID3 + xx;
            acc += vbase[(size_t)(1 + pix) * (3 * Cc)] * wgt[c * 9 + (dy + 1) * 3 + (dx + 1)];
        }
    }
    att[((size_t)b * Nn + 1 + y * GRID3 + x) * Cc + c] += acc;
}

// ---------------------------------------------------------------------------
extern "C" void kernel_launch(void* const* d_in, const int* in_sizes, int n_in,
                              void* d_out, int out_size)
{
    (void)in_sizes; (void)n_in; (void)out_size;
    const float* x     = (const float*)d_in[0];
    const float* Wqkv  = (const float*)d_in[1];
    const float* bqkv  = (const float*)d_in[2];
    const float* Wproj = (const float*)d_in[3];
    const float* bproj = (const float*)d_in[4];
    const float* dwcw  = (const float*)d_in[5];
    const float* dwcb  = (const float*)d_in[6];
    float* out = (float*)d_out;

    float *qkv, *att;
    cudaGetSymbolAddress((void**)&qkv, g_qkv);
    cudaGetSymbolAddress((void**)&att, g_att);

    cudaFuncSetAttribute(attn_kernel, cudaFuncAttributeMaxDynamicSharedMemorySize, SMEM_ATTN);

    const int M = Bn * Nn;  // 50432

    // 1) qkv = x @ W_qkv + b_qkv   (50432 x 2304, K=768)
    {
        dim3 grid(3 * Cc / 128, M / 128);
        sgemm128<<<grid, 256>>>(x, Wqkv, bqkv, qkv, M, 3 * Cc, Cc);
    }
    // 2) attention -> att
    attn_kernel<<<Bn * Hh, 256, SMEM_ATTN>>>(qkv, att);

    // 3) depthwise conv on V, add into att rows 1..196
    {
        size_t total = (size_t)Bn * (GRID3 * GRID3) * Cc;
        int blocks = (int)((total + 255) / 256);
        dwconv_kernel<<<blocks, 256>>>(qkv, dwcw, dwcb, att);
    }
    // 4) out = att @ W_proj + b_proj   (50432 x 768, K=768)
    {
        dim3 grid(Cc / 128, M / 128);
        sgemm128<<<grid, 256>>>(att, Wproj, bproj, out, M, Cc, Cc);
    }
}

// round 3
// speedup vs baseline: 1.4698x; 1.4698x over previous
#include <cuda_runtime.h>
#include <cuda_bf16.h>
#include <cstdint>

// Problem constants
#define Bn   256
#define Nn   197
#define Cc   768
#define Hh   12
#define Dd   64
#define GRID3 14
#define Mtot (Bn * Nn)          // 50432 = 394 * 128

// ---------------------------------------------------------------------------
// Scratch (device globals: allocation-free, graph-capturable)
// ---------------------------------------------------------------------------
__device__ float g_qkv[(size_t)Bn * Nn * 3 * Cc];                 // (B,N,3C)
__device__ float g_att[(size_t)Bn * Nn * Cc];                     // (B,N,C)
__device__ __align__(128) __nv_bfloat16 g_xhi[(size_t)Mtot * Cc]; // A hi (x, then att)
__device__ __align__(128) __nv_bfloat16 g_xlo[(size_t)Mtot * Cc]; // A lo
__device__ __align__(128) __nv_bfloat16 g_w1h[(size_t)3 * Cc * Cc]; // Wqkv^T hi
__device__ __align__(128) __nv_bfloat16 g_w1l[(size_t)3 * Cc * Cc];
__device__ __align__(128) __nv_bfloat16 g_w2h[(size_t)Cc * Cc];     // Wproj^T hi
__device__ __align__(128) __nv_bfloat16 g_w2l[(size_t)Cc * Cc];

// ---------------------------------------------------------------------------
// Helpers (base-ISA only: cp.async, ldmatrix, mma.sync — no tcgen05)
// ---------------------------------------------------------------------------
__device__ __forceinline__ uint32_t smem_u32(const void* p) {
    uint32_t a;
    asm("{ .reg .u64 t; cvta.to.shared.u64 t, %1; cvt.u32.u64 %0, t; }" : "=r"(a) : "l"(p));
    return a;
}
__device__ __forceinline__ void cp16(uint32_t dst, const void* src) {
    asm volatile("cp.async.cg.shared.global [%0], [%1], 16;" :: "r"(dst), "l"(src));
}
__device__ __forceinline__ void ldsm4(uint32_t* r, uint32_t a) {
    asm volatile("ldmatrix.sync.aligned.m8n8.x4.shared.b16 {%0,%1,%2,%3}, [%4];"
        : "=r"(r[0]), "=r"(r[1]), "=r"(r[2]), "=r"(r[3]) : "r"(a));
}
__device__ __forceinline__ void ldsm2(uint32_t* r, uint32_t a) {
    asm volatile("ldmatrix.sync.aligned.m8n8.x2.shared.b16 {%0,%1}, [%2];"
        : "=r"(r[0]), "=r"(r[1]) : "r"(a));
}
__device__ __forceinline__ void mma16816(float* c, const uint32_t* a, const uint32_t* b) {
    asm volatile(
        "mma.sync.aligned.m16n8k16.row.col.f32.bf16.bf16.f32 "
        "{%0,%1,%2,%3}, {%4,%5,%6,%7}, {%8,%9}, {%0,%1,%2,%3};"
        : "+f"(c[0]), "+f"(c[1]), "+f"(c[2]), "+f"(c[3])
        : "r"(a[0]), "r"(a[1]), "r"(a[2]), "r"(a[3]), "r"(b[0]), "r"(b[1]));
}

// ---------------------------------------------------------------------------
// Conversion kernels (fp32 -> bf16 hi/lo split)
// ---------------------------------------------------------------------------
__global__ __launch_bounds__(256) void split_kernel(
    const float* __restrict__ in, __nv_bfloat16* __restrict__ hi,
    __nv_bfloat16* __restrict__ lo, size_t n4)
{
    size_t i = (size_t)blockIdx.x * 256 + threadIdx.x;
    size_t stride = (size_t)gridDim.x * 256;
    for (; i < n4; i += stride) {
        float4 v = ((const float4*)in)[i];
        __nv_bfloat16 h0 = __float2bfloat16(v.x), h1 = __float2bfloat16(v.y);
        __nv_bfloat16 h2 = __float2bfloat16(v.z), h3 = __float2bfloat16(v.w);
        __nv_bfloat162* H = (__nv_bfloat162*)hi;
        __nv_bfloat162* L = (__nv_bfloat162*)lo;
        H[i * 2 + 0] = __nv_bfloat162(h0, h1);
        H[i * 2 + 1] = __nv_bfloat162(h2, h3);
        L[i * 2 + 0] = __nv_bfloat162(__float2bfloat16(v.x - __bfloat162float(h0)),
                                      __float2bfloat16(v.y - __bfloat162float(h1)));
        L[i * 2 + 1] = __nv_bfloat162(__float2bfloat16(v.z - __bfloat162float(h2)),
                                      __float2bfloat16(v.w - __bfloat162float(h3)));
    }
}

// W is (K x N) row-major; emit W^T split as hi/lo [N x K] bf16.
__global__ __launch_bounds__(256) void transpose_split(
    const float* __restrict__ W, __nv_bfloat16* __restrict__ hi,
    __nv_bfloat16* __restrict__ lo, int K, int N)
{
    __shared__ float t[32][33];
    int bx = blockIdx.x * 32, by = blockIdx.y * 32;  // bx over N, by over K
    int tx = threadIdx.x, ty = threadIdx.y;
#pragma unroll
    for (int r = 0; r < 32; r += 8)
        t[ty + r][tx] = W[(size_t)(by + ty + r) * N + bx + tx];
    __syncthreads();
#pragma unroll
    for (int r = 0; r < 32; r += 8) {
        float v = t[tx][ty + r];
        __nv_bfloat16 h = __float2bfloat16(v);
        size_t o = (size_t)(bx + ty + r) * K + by + tx;
        hi[o] = h;
        lo[o] = __float2bfloat16(v - __bfloat162float(h));
    }
}

// ---------------------------------------------------------------------------
// HMMA bf16x3 GEMM: C[M,N] = A[M,768] * B[N,768]^T + bias
// 128x128 CTA tile, 8 warps of 64x32, K-chunks of 64, double-buffered cp.async.
// Padded smem rows (72 bf16 = 144 B) -> conflict-free ldmatrix, no swizzle.
// ---------------------------------------------------------------------------
#define KC   64
#define NCH  (Cc / KC)               // 12
#define LDT  72                      // padded row length (bf16)
#define ROWB (LDT * 2)               // 144 bytes per row
#define TILE_PB (128 * ROWB)         // 18432 bytes per tile
#define STAGE_B (4 * TILE_PB)        // Ah Al Bh Bl = 73728
#define SMEM_GEMM (2 * STAGE_B)      // 147456

__global__ __launch_bounds__(256)
void tc_gemm(const __nv_bfloat16* __restrict__ Ahi, const __nv_bfloat16* __restrict__ Alo,
             const __nv_bfloat16* __restrict__ Bhi, const __nv_bfloat16* __restrict__ Blo,
             const float* __restrict__ bias, float* __restrict__ C, int N)
{
    extern __shared__ char smem[];
    const uint32_t sb = smem_u32(smem);
    const int tid = threadIdx.x, lane = tid & 31, wid = tid >> 5;
    const int m0 = blockIdx.y * 128, n0 = blockIdx.x * 128;
    const int wm = wid >> 2, wn = wid & 3;     // warp tile: rows wm*64, cols wn*32

    // load mapping: 2 threads per row, 4 x 16B chunks each
    const int lrow = tid >> 1;
    const int lc0  = (tid & 1) * 4;
    const __nv_bfloat16* gAh = Ahi + (size_t)(m0 + lrow) * Cc + lc0 * 8;
    const __nv_bfloat16* gAl = Alo + (size_t)(m0 + lrow) * Cc + lc0 * 8;
    const __nv_bfloat16* gBh = Bhi + (size_t)(n0 + lrow) * Cc + lc0 * 8;
    const __nv_bfloat16* gBl = Blo + (size_t)(n0 + lrow) * Cc + lc0 * 8;
    const uint32_t ldst = lrow * ROWB + lc0 * 16;

#define LOADC(c, s) do {                                                \
    uint32_t _d = sb + (s) * STAGE_B + ldst;                            \
    int _k = (c) * KC;                                                  \
    _Pragma("unroll")                                                   \
    for (int q = 0; q < 4; ++q) {                                       \
        cp16(_d + q * 16,               gAh + _k + q * 8);              \
        cp16(_d + TILE_PB + q * 16,     gAl + _k + q * 8);              \
        cp16(_d + 2 * TILE_PB + q * 16, gBh + _k + q * 8);              \
        cp16(_d + 3 * TILE_PB + q * 16, gBl + _k + q * 8);              \
    }                                                                   \
    asm volatile("cp.async.commit_group;" ::: "memory");                \
} while (0)

    float acc[4][4][4];
#pragma unroll
    for (int i = 0; i < 4; i++)
#pragma unroll
        for (int j = 0; j < 4; j++)
#pragma unroll
            for (int k = 0; k < 4; k++) acc[i][j][k] = 0.f;

    LOADC(0, 0);

    // precomputed ldmatrix intra-tile offsets
    const uint32_t aoff = (uint32_t)(wm * 64 + (lane & 15)) * ROWB + ((lane >> 4) << 3) * 2;
    const int lb = lane & 15;
    const uint32_t boff = (uint32_t)(wn * 32 + (lb & 7)) * ROWB + ((lb >> 3) << 3) * 2;

    for (int c = 0; c < NCH; ++c) {
        if (c + 1 < NCH) {
            LOADC(c + 1, (c + 1) & 1);
            asm volatile("cp.async.wait_group 1;" ::: "memory");
        } else {
            asm volatile("cp.async.wait_group 0;" ::: "memory");
        }
        __syncthreads();

        const uint32_t S = sb + (c & 1) * STAGE_B;
#pragma unroll
        for (int ks = 0; ks < 4; ++ks) {
            uint32_t ah[4][4], al[4][4], bh[4][2], bl[4][2];
#pragma unroll
            for (int im = 0; im < 4; ++im) {
                uint32_t a = S + aoff + (uint32_t)(im * 16) * ROWB + ks * 32;
                ldsm4(ah[im], a);
                ldsm4(al[im], a + TILE_PB);
            }
#pragma unroll
            for (int jn = 0; jn < 4; ++jn) {
                uint32_t a = S + 2 * TILE_PB + boff + (uint32_t)(jn * 8) * ROWB + ks * 32;
                ldsm2(bh[jn], a);
                ldsm2(bl[jn], a + TILE_PB);
            }
#pragma unroll
            for (int im = 0; im < 4; ++im)
#pragma unroll
                for (int jn = 0; jn < 4; ++jn) {
                    mma16816(acc[im][jn], ah[im], bh[jn]);
                    mma16816(acc[im][jn], ah[im], bl[jn]);
                    mma16816(acc[im][jn], al[im], bh[jn]);
                }
        }
        __syncthreads();
    }

    // epilogue: direct global stores with bias
    const int g = lane >> 2, tc = (lane & 3) * 2;
#pragma unroll
    for (int im = 0; im < 4; ++im) {
        int row = m0 + wm * 64 + im * 16 + g;
#pragma unroll
        for (int jn = 0; jn < 4; ++jn) {
            int col = n0 + wn * 32 + jn * 8 + tc;
            float b0 = bias[col], b1 = bias[col + 1];
            float2 v0 = make_float2(acc[im][jn][0] + b0, acc[im][jn][1] + b1);
            float2 v1 = make_float2(acc[im][jn][2] + b0, acc[im][jn][3] + b1);
            *(float2*)(C + (size_t)row * N + col)       = v0;
            *(float2*)(C + (size_t)(row + 8) * N + col) = v1;
        }
    }
#undef LOADC
}

// ---------------------------------------------------------------------------
// Attention: one CTA per (b,h). fp32, smem-resident K/V, vectorized LDS.128.
// ---------------------------------------------------------------------------
#define KV_STRIDE 68
#define SMEM_ATTN ((2 * Nn * KV_STRIDE + 8 * 200 + 8 * 64) * (int)sizeof(float))

__global__ __launch_bounds__(256) void attn_kernel(
    const float* __restrict__ qkv, float* __restrict__ att)
{
    extern __shared__ float fsm[];
    float* Ks = fsm;
    float* Vs = Ks + Nn * KV_STRIDE;
    float* pb = Vs + Nn * KV_STRIDE;
    float* qb = pb + 8 * 200;

    const int bh = blockIdx.x;
    const int b = bh / Hh, h = bh % Hh;
    const int tid = threadIdx.x, lane = tid & 31, w = tid >> 5;

    const float* base = qkv + (size_t)b * Nn * (3 * Cc) + h * Dd;

    for (int idx = tid; idx < Nn * Dd; idx += 256) {
        int j = idx >> 6, d = idx & 63;
        size_t roff = (size_t)j * (3 * Cc);
        Ks[j * KV_STRIDE + d] = base[roff + Cc + d];
        Vs[j * KV_STRIDE + d] = base[roff + 2 * Cc + d];
    }
    __syncthreads();

    float* pw = pb + w * 200;
    float* qw = qb + w * 64;

    for (int rowi = w; rowi < Nn; rowi += 8) {
        qw[lane]      = base[(size_t)rowi * (3 * Cc) + lane];
        qw[lane + 32] = base[(size_t)rowi * (3 * Cc) + lane + 32];
        __syncwarp();

        float4 qr[16];
#pragma unroll
        for (int d4 = 0; d4 < 16; ++d4) qr[d4] = *(const float4*)(qw + 4 * d4);

        float s[7];
        float mx = -1e30f;
#pragma unroll
        for (int jj = 0; jj < 7; ++jj) {
            int j = lane + jj * 32;
            float a = -1e30f;
            if (j < Nn) {
                const float* kp = Ks + j * KV_STRIDE;
                float acc = 0.f;
#pragma unroll
                for (int d4 = 0; d4 < 16; ++d4) {
                    float4 kv = *(const float4*)(kp + 4 * d4);
                    acc += qr[d4].x * kv.x + qr[d4].y * kv.y
                         + qr[d4].z * kv.z + qr[d4].w * kv.w;
                }
                a = acc * 0.125f;
            }
            s[jj] = a;
            mx = fmaxf(mx, a);
        }
#pragma unroll
        for (int o = 16; o; o >>= 1) mx = fmaxf(mx, __shfl_xor_sync(~0u, mx, o));

        float sum = 0.f;
#pragma unroll
        for (int jj = 0; jj < 7; ++jj) { s[jj] = __expf(s[jj] - mx); sum += s[jj]; }
#pragma unroll
        for (int o = 16; o; o >>= 1) sum += __shfl_xor_sync(~0u, sum, o);
        float inv = 1.f / sum;
#pragma unroll
        for (int jj = 0; jj < 7; ++jj) {
            int j = lane + jj * 32;
            if (j < Nn) pw[j] = s[jj] * inv;
        }
        __syncwarp();

        float a0 = 0.f, a1 = 0.f;
        for (int j = 0; j < 196; j += 4) {
            float4 p4 = *(const float4*)(pw + j);
            const float* v0 = Vs + j * KV_STRIDE;
            a0 += p4.x * v0[lane];                 a1 += p4.x * v0[lane + 32];
            a0 += p4.y * v0[KV_STRIDE + lane];     a1 += p4.y * v0[KV_STRIDE + lane + 32];
            a0 += p4.z * v0[2 * KV_STRIDE + lane]; a1 += p4.z * v0[2 * KV_STRIDE + lane + 32];
            a0 += p4.w * v0[3 * KV_STRIDE + lane]; a1 += p4.w * v0[3 * KV_STRIDE + lane + 32];
        }
        {
            float p = pw[196];
            a0 += p * Vs[196 * KV_STRIDE + lane];
            a1 += p * Vs[196 * KV_STRIDE + lane + 32];
        }
        float* o = att + ((size_t)(b * Nn + rowi)) * Cc + h * Dd;
        o[lane]      = a0;
        o[lane + 32] = a1;
        __syncwarp();
    }
}

// ---------------------------------------------------------------------------
// Depthwise 3x3 conv on V, accumulate into att rows 1..196
// ---------------------------------------------------------------------------
__global__ __launch_bounds__(256) void dwconv_kernel(
    const float* __restrict__ qkv, const float* __restrict__ wgt,
    const float* __restrict__ bias, float* __restrict__ att)
{
    size_t idx = (size_t)blockIdx.x * 256 + threadIdx.x;
    const size_t total = (size_t)Bn * (GRID3 * GRID3) * Cc;
    if (idx >= total) return;

    int c = idx % Cc;
    size_t t = idx / Cc;
    int x = t % GRID3; t /= GRID3;
    int y = t % GRID3;
    int b = t / GRID3;

    const float* vbase = qkv + (size_t)b * Nn * (3 * Cc) + 2 * Cc + c;
    float acc = bias[c];
#pragma unroll
    for (int dy = -1; dy <= 1; ++dy) {
        int yy = y + dy;
        if (yy < 0 || yy >= GRID3) continue;
#pragma unroll
        for (int dx = -1; dx <= 1; ++dx) {
            int xx = x + dx;
            if (xx < 0 || xx >= GRID3) continue;
            int pix = yy * GRID3 + xx;
            acc += vbase[(size_t)(1 + pix) * (3 * Cc)] * wgt[c * 9 + (dy + 1) * 3 + (dx + 1)];
        }
    }
    att[((size_t)b * Nn + 1 + y * GRID3 + x) * Cc + c] += acc;
}

// ---------------------------------------------------------------------------
extern "C" void kernel_launch(void* const* d_in, const int* in_sizes, int n_in,
                              void* d_out, int out_size)
{
    (void)in_sizes; (void)n_in; (void)out_size;
    const float* x     = (const float*)d_in[0];
    const float* Wqkv  = (const float*)d_in[1];
    const float* bqkv  = (const float*)d_in[2];
    const float* Wproj = (const float*)d_in[3];
    const float* bproj = (const float*)d_in[4];
    const float* dwcw  = (const float*)d_in[5];
    const float* dwcb  = (const float*)d_in[6];
    float* out = (float*)d_out;

    float *qkv, *att;
    __nv_bfloat16 *xhi, *xlo, *w1h, *w1l, *w2h, *w2l;
    cudaGetSymbolAddress((void**)&qkv, g_qkv);
    cudaGetSymbolAddress((void**)&att, g_att);
    cudaGetSymbolAddress((void**)&xhi, g_xhi);
    cudaGetSymbolAddress((void**)&xlo, g_xlo);
    cudaGetSymbolAddress((void**)&w1h, g_w1h);
    cudaGetSymbolAddress((void**)&w1l, g_w1l);
    cudaGetSymbolAddress((void**)&w2h, g_w2h);
    cudaGetSymbolAddress((void**)&w2l, g_w2l);

    cudaFuncSetAttribute(tc_gemm, cudaFuncAttributeMaxDynamicSharedMemorySize, SMEM_GEMM);
    cudaFuncSetAttribute(attn_kernel, cudaFuncAttributeMaxDynamicSharedMemorySize, SMEM_ATTN);

    const size_t nX4 = (size_t)Mtot * Cc / 4;
    const int splitBlocks = 2048;

    // 1) split x -> bf16 hi/lo ; transpose-split Wqkv
    split_kernel<<<splitBlocks, 256>>>(x, xhi, xlo, nX4);
    {
        dim3 g(3 * Cc / 32, Cc / 32), blk(32, 8);
        transpose_split<<<g, blk>>>(Wqkv, w1h, w1l, Cc, 3 * Cc);
    }
    // 2) qkv = x @ Wqkv + b  (HMMA bf16x3)
    {
        dim3 grid(3 * Cc / 128, Mtot / 128);
        tc_gemm<<<grid, 256, SMEM_GEMM>>>(xhi, xlo, w1h, w1l, bqkv, qkv, 3 * Cc);
    }
    // 3) attention -> att
    attn_kernel<<<Bn * Hh, 256, SMEM_ATTN>>>(qkv, att);
    // 4) depthwise conv on V, add into att
    {
        size_t total = (size_t)Bn * (GRID3 * GRID3) * Cc;
        dwconv_kernel<<<(int)((total + 255) / 256), 256>>>(qkv, dwcw, dwcb, att);
    }
    // 5) split att ; transpose-split Wproj ; out = att @ Wproj + b
    split_kernel<<<splitBlocks, 256>>>(att, xhi, xlo, nX4);
    {
        dim3 g(Cc / 32, Cc / 32), blk(32, 8);
        transpose_split<<<g, blk>>>(Wproj, w2h, w2l, Cc, Cc);
    }
    {
        dim3 grid(Cc / 128, Mtot / 128);
        tc_gemm<<<grid, 256, SMEM_GEMM>>>(xhi, xlo, w2h, w2l, bproj, out, Cc);
    }
}

// round 4
// speedup vs baseline: 2.0264x; 1.3787x over previous
#include <cuda_runtime.h>
#include <cuda_bf16.h>
#include <cstdint>

// Problem constants
#define Bn   256
#define Nn   197
#define Cc   768
#define Hh   12
#define Dd   64
#define GRID3 14
#define Mtot (Bn * Nn)          // 50432 = 394 * 128
#define BH   (Bn * Hh)          // 3072
#define NPAD 256                // padded sequence for attention buffers

// ---------------------------------------------------------------------------
// Scratch (device globals: allocation-free, graph-capturable, zero-init)
// ---------------------------------------------------------------------------
__device__ __align__(128) __nv_bfloat16 g_xhi[(size_t)Mtot * Cc]; // A hi (x, then att)
__device__ __align__(128) __nv_bfloat16 g_xlo[(size_t)Mtot * Cc]; // A lo
__device__ __align__(128) __nv_bfloat16 g_w1h[(size_t)3 * Cc * Cc];
__device__ __align__(128) __nv_bfloat16 g_w1l[(size_t)3 * Cc * Cc];
__device__ __align__(128) __nv_bfloat16 g_w2h[(size_t)Cc * Cc];
__device__ __align__(128) __nv_bfloat16 g_w2l[(size_t)Cc * Cc];
// per-(b,h) padded Q/K/V, hi/lo split: [BH][NPAD][64]
__device__ __align__(128) __nv_bfloat16 g_Qh[(size_t)BH * NPAD * Dd];
__device__ __align__(128) __nv_bfloat16 g_Ql[(size_t)BH * NPAD * Dd];
__device__ __align__(128) __nv_bfloat16 g_Kh[(size_t)BH * NPAD * Dd];
__device__ __align__(128) __nv_bfloat16 g_Kl[(size_t)BH * NPAD * Dd];
__device__ __align__(128) __nv_bfloat16 g_Vh[(size_t)BH * NPAD * Dd];
__device__ __align__(128) __nv_bfloat16 g_Vl[(size_t)BH * NPAD * Dd];

// ---------------------------------------------------------------------------
// Helpers (base-ISA only)
// ---------------------------------------------------------------------------
__device__ __forceinline__ uint32_t smem_u32(const void* p) {
    uint32_t a;
    asm("{ .reg .u64 t; cvta.to.shared.u64 t, %1; cvt.u32.u64 %0, t; }" : "=r"(a) : "l"(p));
    return a;
}
__device__ __forceinline__ void cp16(uint32_t dst, const void* src) {
    asm volatile("cp.async.cg.shared.global [%0], [%1], 16;" :: "r"(dst), "l"(src));
}
__device__ __forceinline__ void ldsm4(uint32_t* r, uint32_t a) {
    asm volatile("ldmatrix.sync.aligned.m8n8.x4.shared.b16 {%0,%1,%2,%3}, [%4];"
        : "=r"(r[0]), "=r"(r[1]), "=r"(r[2]), "=r"(r[3]) : "r"(a));
}
__device__ __forceinline__ void ldsm2(uint32_t* r, uint32_t a) {
    asm volatile("ldmatrix.sync.aligned.m8n8.x2.shared.b16 {%0,%1}, [%2];"
        : "=r"(r[0]), "=r"(r[1]) : "r"(a));
}
__device__ __forceinline__ void ldsm2t(uint32_t* r, uint32_t a) {
    asm volatile("ldmatrix.sync.aligned.m8n8.x2.trans.shared.b16 {%0,%1}, [%2];"
        : "=r"(r[0]), "=r"(r[1]) : "r"(a));
}
__device__ __forceinline__ void mma16816(float* c, const uint32_t* a, const uint32_t* b) {
    asm volatile(
        "mma.sync.aligned.m16n8k16.row.col.f32.bf16.bf16.f32 "
        "{%0,%1,%2,%3}, {%4,%5,%6,%7}, {%8,%9}, {%0,%1,%2,%3};"
        : "+f"(c[0]), "+f"(c[1]), "+f"(c[2]), "+f"(c[3])
        : "r"(a[0]), "r"(a[1]), "r"(a[2]), "r"(a[3]), "r"(b[0]), "r"(b[1]));
}
__device__ __forceinline__ void split2(float x, float y, uint32_t& hi, uint32_t& lo) {
    __nv_bfloat16 hx = __float2bfloat16(x), hy = __float2bfloat16(y);
    __nv_bfloat162 H(hx, hy);
    __nv_bfloat162 L(__float2bfloat16(x - __bfloat162float(hx)),
                     __float2bfloat16(y - __bfloat162float(hy)));
    hi = *reinterpret_cast<uint32_t*>(&H);
    lo = *reinterpret_cast<uint32_t*>(&L);
}

// ---------------------------------------------------------------------------
// Conversion kernels
// ---------------------------------------------------------------------------
__global__ __launch_bounds__(256) void split_kernel(
    const float* __restrict__ in, __nv_bfloat16* __restrict__ hi,
    __nv_bfloat16* __restrict__ lo, size_t n4)
{
    size_t i = (size_t)blockIdx.x * 256 + threadIdx.x;
    size_t stride = (size_t)gridDim.x * 256;
    for (; i < n4; i += stride) {
        float4 v = ((const float4*)in)[i];
        uint32_t h0, l0, h1, l1;
        split2(v.x, v.y, h0, l0);
        split2(v.z, v.w, h1, l1);
        ((uint32_t*)hi)[i * 2 + 0] = h0;
        ((uint32_t*)hi)[i * 2 + 1] = h1;
        ((uint32_t*)lo)[i * 2 + 0] = l0;
        ((uint32_t*)lo)[i * 2 + 1] = l1;
    }
}

// W is (K x N) row-major; emit W^T split as hi/lo [N x K] bf16.
__global__ __launch_bounds__(256) void transpose_split(
    const float* __restrict__ W, __nv_bfloat16* __restrict__ hi,
    __nv_bfloat16* __restrict__ lo, int K, int N)
{
    __shared__ float t[32][33];
    int bx = blockIdx.x * 32, by = blockIdx.y * 32;
    int tx = threadIdx.x, ty = threadIdx.y;
#pragma unroll
    for (int r = 0; r < 32; r += 8)
        t[ty + r][tx] = W[(size_t)(by + ty + r) * N + bx + tx];
    __syncthreads();
#pragma unroll
    for (int r = 0; r < 32; r += 8) {
        float v = t[tx][ty + r];
        __nv_bfloat16 h = __float2bfloat16(v);
        size_t o = (size_t)(bx + ty + r) * K + by + tx;
        hi[o] = h;
        lo[o] = __float2bfloat16(v - __bfloat162float(h));
    }
}

// zero the padding rows (197..255) of V buffers so 0*garbage never produces NaN
__global__ __launch_bounds__(256) void zero_vpad(
    __nv_bfloat16* __restrict__ Vh, __nv_bfloat16* __restrict__ Vl)
{
    size_t idx = (size_t)blockIdx.x * 256 + threadIdx.x;
    const size_t total = (size_t)BH * (NPAD - Nn) * Dd;
    if (idx >= total) return;
    int d = idx % Dd;
    size_t t = idx / Dd;
    int r = Nn + (int)(t % (NPAD - Nn));
    int bh = (int)(t / (NPAD - Nn));
    size_t o = ((size_t)bh * NPAD + r) * Dd + d;
    Vh[o] = __float2bfloat16(0.f);
    Vl[o] = __float2bfloat16(0.f);
}

// ---------------------------------------------------------------------------
// HMMA bf16x3 GEMM: C[M,N] = A[M,768]*B[N,768]^T + bias
// MODE 0: write fp32 C. MODE 1 (qkv): split-write into g_Q/K/V hi/lo padded.
// ---------------------------------------------------------------------------
#define KC   64
#define NCH  (Cc / KC)
#define LDT  72
#define ROWB (LDT * 2)               // 144 B
#define TILE_PB (128 * ROWB)
#define STAGE_B (4 * TILE_PB)
#define SMEM_GEMM (2 * STAGE_B)      // 147456

template<int MODE>
__global__ __launch_bounds__(256)
void tc_gemm(const __nv_bfloat16* __restrict__ Ahi, const __nv_bfloat16* __restrict__ Alo,
             const __nv_bfloat16* __restrict__ Bhi, const __nv_bfloat16* __restrict__ Blo,
             const float* __restrict__ bias, float* __restrict__ C, int N,
             __nv_bfloat16* Qh, __nv_bfloat16* Ql,
             __nv_bfloat16* Kh, __nv_bfloat16* Kl,
             __nv_bfloat16* Vh, __nv_bfloat16* Vl)
{
    extern __shared__ char smem[];
    const uint32_t sb = smem_u32(smem);
    const int tid = threadIdx.x, lane = tid & 31, wid = tid >> 5;
    const int m0 = blockIdx.y * 128, n0 = blockIdx.x * 128;
    const int wm = wid >> 2, wn = wid & 3;

    const int lrow = tid >> 1;
    const int lc0  = (tid & 1) * 4;
    const __nv_bfloat16* gAh = Ahi + (size_t)(m0 + lrow) * Cc + lc0 * 8;
    const __nv_bfloat16* gAl = Alo + (size_t)(m0 + lrow) * Cc + lc0 * 8;
    const __nv_bfloat16* gBh = Bhi + (size_t)(n0 + lrow) * Cc + lc0 * 8;
    const __nv_bfloat16* gBl = Blo + (size_t)(n0 + lrow) * Cc + lc0 * 8;
    const uint32_t ldst = lrow * ROWB + lc0 * 16;

#define LOADC(c, s) do {                                                \
    uint32_t _d = sb + (s) * STAGE_B + ldst;                            \
    int _k = (c) * KC;                                                  \
    _Pragma("unroll")                                                   \
    for (int q = 0; q < 4; ++q) {                                       \
        cp16(_d + q * 16,               gAh + _k + q * 8);              \
        cp16(_d + TILE_PB + q * 16,     gAl + _k + q * 8);              \
        cp16(_d + 2 * TILE_PB + q * 16, gBh + _k + q * 8);              \
        cp16(_d + 3 * TILE_PB + q * 16, gBl + _k + q * 8);              \
    }                                                                   \
    asm volatile("cp.async.commit_group;" ::: "memory");                \
} while (0)

    float acc[4][4][4];
#pragma unroll
    for (int i = 0; i < 4; i++)
#pragma unroll
        for (int j = 0; j < 4; j++)
#pragma unroll
            for (int k = 0; k < 4; k++) acc[i][j][k] = 0.f;

    LOADC(0, 0);

    const uint32_t aoff = (uint32_t)(wm * 64 + (lane & 15)) * ROWB + ((lane >> 4) << 3) * 2;
    const int lb = lane & 15;
    const uint32_t boff = (uint32_t)(wn * 32 + (lb & 7)) * ROWB + ((lb >> 3) << 3) * 2;

    for (int c = 0; c < NCH; ++c) {
        if (c + 1 < NCH) {
            LOADC(c + 1, (c + 1) & 1);
            asm volatile("cp.async.wait_group 1;" ::: "memory");
        } else {
            asm volatile("cp.async.wait_group 0;" ::: "memory");
        }
        __syncthreads();

        const uint32_t S = sb + (c & 1) * STAGE_B;
#pragma unroll
        for (int ks = 0; ks < 4; ++ks) {
            uint32_t ah[4][4], al[4][4], bh[4][2], bl[4][2];
#pragma unroll
            for (int im = 0; im < 4; ++im) {
                uint32_t a = S + aoff + (uint32_t)(im * 16) * ROWB + ks * 32;
                ldsm4(ah[im], a);
                ldsm4(al[im], a + TILE_PB);
            }
#pragma unroll
            for (int jn = 0; jn < 4; ++jn) {
                uint32_t a = S + 2 * TILE_PB + boff + (uint32_t)(jn * 8) * ROWB + ks * 32;
                ldsm2(bh[jn], a);
                ldsm2(bl[jn], a + TILE_PB);
            }
#pragma unroll
            for (int im = 0; im < 4; ++im)
#pragma unroll
                for (int jn = 0; jn < 4; ++jn) {
                    mma16816(acc[im][jn], ah[im], bh[jn]);
                    mma16816(acc[im][jn], ah[im], bl[jn]);
                    mma16816(acc[im][jn], al[im], bh[jn]);
                }
        }
        __syncthreads();
    }

    const int g = lane >> 2, tc = (lane & 3) * 2;
    if (MODE == 0) {
#pragma unroll
        for (int im = 0; im < 4; ++im) {
            int row = m0 + wm * 64 + im * 16 + g;
#pragma unroll
            for (int jn = 0; jn < 4; ++jn) {
                int col = n0 + wn * 32 + jn * 8 + tc;
                float b0 = bias[col], b1 = bias[col + 1];
                float2 v0 = make_float2(acc[im][jn][0] + b0, acc[im][jn][1] + b1);
                float2 v1 = make_float2(acc[im][jn][2] + b0, acc[im][jn][3] + b1);
                *(float2*)(C + (size_t)row * N + col)       = v0;
                *(float2*)(C + (size_t)(row + 8) * N + col) = v1;
            }
        }
    } else {
#pragma unroll
        for (int jn = 0; jn < 4; ++jn) {
            int col = n0 + wn * 32 + jn * 8 + tc;
            int t = col / Cc, rem = col - t * Cc;
            int hh = rem >> 6, dd = rem & 63;
            __nv_bfloat16* BHp = (t == 0) ? Qh : (t == 1) ? Kh : Vh;
            __nv_bfloat16* BLp = (t == 0) ? Ql : (t == 1) ? Kl : Vl;
            float b0 = bias[col], b1 = bias[col + 1];
#pragma unroll
            for (int im = 0; im < 4; ++im) {
                int row0 = m0 + wm * 64 + im * 16 + g;
#pragma unroll
                for (int rr = 0; rr < 2; ++rr) {
                    int row = row0 + rr * 8;
                    int bb = row / Nn, nn = row - bb * Nn;
                    size_t o = (((size_t)bb * Hh + hh) * NPAD + nn) * Dd + dd;
                    uint32_t hi, lo;
                    split2(acc[im][jn][rr * 2] + b0, acc[im][jn][rr * 2 + 1] + b1, hi, lo);
                    *(uint32_t*)(BHp + o) = hi;
                    *(uint32_t*)(BLp + o) = lo;
                }
            }
        }
    }
#undef LOADC
}

// ---------------------------------------------------------------------------
// Flash attention on HMMA: CTA = (mtile 64 queries) x (b,h). K/V chunks of 64
// keys double-buffered. S = Q@K^T (hi/lo x3), online softmax, P packed from
// accumulators (hi/lo), PV via ldmatrix.trans on V (hi/lo x3).
// Output written as bf16 hi/lo straight into the proj-GEMM A buffers.
// ---------------------------------------------------------------------------
#define FA_QB   9216                      // 64 rows * 144B
#define FA_STG  (4 * FA_QB)               // Kh Kl Vh Vl
#define SMEM_FA (2 * FA_QB + 2 * FA_STG)  // 92160

__global__ __launch_bounds__(128) void flash_attn(
    const __nv_bfloat16* __restrict__ Qh, const __nv_bfloat16* __restrict__ Ql,
    const __nv_bfloat16* __restrict__ Kh, const __nv_bfloat16* __restrict__ Kl,
    const __nv_bfloat16* __restrict__ Vh, const __nv_bfloat16* __restrict__ Vl,
    __nv_bfloat16* __restrict__ xhi, __nv_bfloat16* __restrict__ xlo)
{
    extern __shared__ char smem[];
    const uint32_t sb = smem_u32(smem);
    const int mt = blockIdx.x, bh = blockIdx.y;
    const int b = bh / Hh, h = bh % Hh;
    const int tid = threadIdx.x, lane = tid & 31, w = tid >> 5;

    const uint32_t SQh = sb, SQl = sb + FA_QB;
    // stage s: base sb + 2*FA_QB + s*FA_STG; layout: Kh, Kl, Vh, Vl

    // --- load Q tile (64 rows) ---
    {
        int row = tid >> 1, half = tid & 1;
        size_t gq = ((size_t)bh * NPAD + mt * 64 + row) * Dd + half * 32;
        uint32_t d = SQh + row * ROWB + half * 64;
#pragma unroll
        for (int i = 0; i < 4; ++i) {
            cp16(d + i * 16, Qh + gq + i * 8);
            cp16(d + FA_QB + i * 16, Ql + gq + i * 8);
        }
    }
#define LKV(c, s) do {                                                       \
    int row = tid >> 1, half = tid & 1;                                      \
    size_t gk = ((size_t)bh * NPAD + (c) * 64 + row) * Dd + half * 32;       \
    uint32_t d = sb + 2 * FA_QB + (s) * FA_STG + row * ROWB + half * 64;     \
    _Pragma("unroll")                                                        \
    for (int i = 0; i < 4; ++i) {                                            \
        cp16(d + i * 16,              Kh + gk + i * 8);                      \
        cp16(d + FA_QB + i * 16,      Kl + gk + i * 8);                      \
        cp16(d + 2 * FA_QB + i * 16,  Vh + gk + i * 8);                      \
        cp16(d + 3 * FA_QB + i * 16,  Vl + gk + i * 8);                      \
    }                                                                        \
    asm volatile("cp.async.commit_group;" ::: "memory");                     \
} while (0)

    LKV(0, 0);   // group 0 (includes Q)
    LKV(1, 1);   // group 1

    const uint32_t aoff = (uint32_t)(w * 16 + (lane & 15)) * ROWB + ((lane >> 4) << 3) * 2;
    const int lb = lane & 15;
    const uint32_t koff = (uint32_t)(lb & 7) * ROWB + ((lb >> 3) << 3) * 2;
    const uint32_t voff = (uint32_t)(lane & 15) * ROWB;

    float oA[8][4];
#pragma unroll
    for (int i = 0; i < 8; i++)
#pragma unroll
        for (int j = 0; j < 4; j++) oA[i][j] = 0.f;
    float mx[2] = {-1e30f, -1e30f}, sum[2] = {0.f, 0.f};
    const int tc = (lane & 3) * 2;

    for (int c = 0; c < 4; ++c) {
        if (c < 3) asm volatile("cp.async.wait_group 1;" ::: "memory");
        else       asm volatile("cp.async.wait_group 0;" ::: "memory");
        __syncthreads();

        const uint32_t SK = sb + 2 * FA_QB + (c & 1) * FA_STG;
        const uint32_t SV = SK + 2 * FA_QB;

        // ---- S = Q @ K^T (3 passes) ----
        float sA[8][4];
#pragma unroll
        for (int i = 0; i < 8; i++)
#pragma unroll
            for (int j = 0; j < 4; j++) sA[i][j] = 0.f;
#pragma unroll
        for (int kk = 0; kk < 4; ++kk) {
            uint32_t qh4[4], ql4[4];
            ldsm4(qh4, SQh + aoff + kk * 32);
            ldsm4(ql4, SQl + aoff + kk * 32);
#pragma unroll
            for (int nt = 0; nt < 8; ++nt) {
                uint32_t kh2[2], kl2[2];
                uint32_t ka = SK + koff + (uint32_t)(nt * 8) * ROWB + kk * 32;
                ldsm2(kh2, ka);
                ldsm2(kl2, ka + FA_QB);
                mma16816(sA[nt], qh4, kh2);
                mma16816(sA[nt], qh4, kl2);
                mma16816(sA[nt], ql4, kh2);
            }
        }

        // ---- online softmax ----
#pragma unroll
        for (int rt = 0; rt < 2; ++rt) {
            float m = -1e30f;
#pragma unroll
            for (int nt = 0; nt < 8; ++nt) {
                int j = c * 64 + nt * 8 + tc;
                float v0 = (j < Nn)     ? sA[nt][rt * 2]     * 0.125f : -1e30f;
                float v1 = (j + 1 < Nn) ? sA[nt][rt * 2 + 1] * 0.125f : -1e30f;
                sA[nt][rt * 2] = v0;
                sA[nt][rt * 2 + 1] = v1;
                m = fmaxf(m, fmaxf(v0, v1));
            }
            m = fmaxf(m, __shfl_xor_sync(~0u, m, 1));
            m = fmaxf(m, __shfl_xor_sync(~0u, m, 2));
            float mn = fmaxf(mx[rt], m);
            float scl = __expf(mx[rt] - mn);
            mx[rt] = mn;
            float ls = 0.f;
#pragma unroll
            for (int nt = 0; nt < 8; ++nt) {
                float p0 = __expf(sA[nt][rt * 2] - mn);
                float p1 = __expf(sA[nt][rt * 2 + 1] - mn);
                sA[nt][rt * 2] = p0;
                sA[nt][rt * 2 + 1] = p1;
                ls += p0 + p1;
                oA[nt][rt * 2] *= scl;
                oA[nt][rt * 2 + 1] *= scl;
            }
            ls += __shfl_xor_sync(~0u, ls, 1);
            ls += __shfl_xor_sync(~0u, ls, 2);
            sum[rt] = sum[rt] * scl + ls;
        }

        // ---- out += P @ V (3 passes) ----
#pragma unroll
        for (int kk = 0; kk < 4; ++kk) {
            uint32_t ph[4], pl[4];
            split2(sA[2 * kk][0],     sA[2 * kk][1],     ph[0], pl[0]);
            split2(sA[2 * kk][2],     sA[2 * kk][3],     ph[1], pl[1]);
            split2(sA[2 * kk + 1][0], sA[2 * kk + 1][1], ph[2], pl[2]);
            split2(sA[2 * kk + 1][2], sA[2 * kk + 1][3], ph[3], pl[3]);
#pragma unroll
            for (int nd = 0; nd < 8; ++nd) {
                uint32_t vh2[2], vl2[2];
                uint32_t va = SV + voff + (uint32_t)(kk * 16) * ROWB + nd * 16;
                ldsm2t(vh2, va);
                ldsm2t(vl2, va + FA_QB);
                mma16816(oA[nd], ph, vh2);
                mma16816(oA[nd], ph, vl2);
                mma16816(oA[nd], pl, vh2);
            }
        }
        __syncthreads();
        if (c + 2 < 4) LKV(c + 2, c & 1);
    }

    // ---- epilogue: divide by sum, split-write into proj A buffers ----
    const float i0 = 1.f / sum[0], i1 = 1.f / sum[1];
    const int g = lane >> 2;
    const int q0 = mt * 64 + w * 16 + g;
    const int dcol = h * Dd + tc;
#pragma unroll
    for (int rr = 0; rr < 2; ++rr) {
        int q = q0 + rr * 8;
        if (q >= Nn) continue;
        float inv = rr ? i1 : i0;
        size_t o = ((size_t)b * Nn + q) * Cc + dcol;
#pragma unroll
        for (int nd = 0; nd < 8; ++nd) {
            uint32_t hi, lo;
            split2(oA[nd][rr * 2] * inv, oA[nd][rr * 2 + 1] * inv, hi, lo);
            *(uint32_t*)(xhi + o + nd * 8) = hi;
            *(uint32_t*)(xlo + o + nd * 8) = lo;
        }
    }
#undef LKV
}

// ---------------------------------------------------------------------------
// Fused depthwise 3x3 conv on V + residual add into (already split) att:
// val = (xhi+xlo) + conv(V); re-split in place. Rows 1..196 only.
// ---------------------------------------------------------------------------
__global__ __launch_bounds__(256) void conv_split(
    const __nv_bfloat16* __restrict__ Vh, const __nv_bfloat16* __restrict__ Vl,
    const float* __restrict__ wgt, const float* __restrict__ bias,
    __nv_bfloat16* __restrict__ xhi, __nv_bfloat16* __restrict__ xlo)
{
    size_t idx = (size_t)blockIdx.x * 256 + threadIdx.x;
    const size_t total = (size_t)Bn * (GRID3 * GRID3) * Cc;
    if (idx >= total) return;

    int c = idx % Cc;
    size_t t = idx / Cc;
    int x = t % GRID3; t /= GRID3;
    int y = t % GRID3;
    int b = (int)(t / GRID3);

    int hh = c >> 6, dd = c & 63;
    const size_t vb = ((size_t)(b * Hh + hh) * NPAD) * Dd + dd;

    float acc = bias[c];
#pragma unroll
    for (int dy = -1; dy <= 1; ++dy) {
        int yy = y + dy;
        if (yy < 0 || yy >= GRID3) continue;
#pragma unroll
        for (int dx = -1; dx <= 1; ++dx) {
            int xx = x + dx;
            if (xx < 0 || xx >= GRID3) continue;
            size_t a = vb + (size_t)(1 + yy * GRID3 + xx) * Dd;
            float v = __bfloat162float(Vh[a]) + __bfloat162float(Vl[a]);
            acc += v * wgt[c * 9 + (dy + 1) * 3 + (dx + 1)];
        }
    }
    size_t o = ((size_t)b * Nn + 1 + y * GRID3 + x) * Cc + c;
    float val = __bfloat162float(xhi[o]) + __bfloat162float(xlo[o]) + acc;
    __nv_bfloat16 hi = __float2bfloat16(val);
    xhi[o] = hi;
    xlo[o] = __float2bfloat16(val - __bfloat162float(hi));
}

// ---------------------------------------------------------------------------
extern "C" void kernel_launch(void* const* d_in, const int* in_sizes, int n_in,
                              void* d_out, int out_size)
{
    (void)in_sizes; (void)n_in; (void)out_size;
    const float* x     = (const float*)d_in[0];
    const float* Wqkv  = (const float*)d_in[1];
    const float* bqkv  = (const float*)d_in[2];
    const float* Wproj = (const float*)d_in[3];
    const float* bproj = (const float*)d_in[4];
    const float* dwcw  = (const float*)d_in[5];
    const float* dwcb  = (const float*)d_in[6];
    float* out = (float*)d_out;

    __nv_bfloat16 *xhi, *xlo, *w1h, *w1l, *w2h, *w2l;
    __nv_bfloat16 *Qh, *Ql, *Kh, *Kl, *Vh, *Vl;
    cudaGetSymbolAddress((void**)&xhi, g_xhi);
    cudaGetSymbolAddress((void**)&xlo, g_xlo);
    cudaGetSymbolAddress((void**)&w1h, g_w1h);
    cudaGetSymbolAddress((void**)&w1l, g_w1l);
    cudaGetSymbolAddress((void**)&w2h, g_w2h);
    cudaGetSymbolAddress((void**)&w2l, g_w2l);
    cudaGetSymbolAddress((void**)&Qh, g_Qh);
    cudaGetSymbolAddress((void**)&Ql, g_Ql);
    cudaGetSymbolAddress((void**)&Kh, g_Kh);
    cudaGetSymbolAddress((void**)&Kl, g_Kl);
    cudaGetSymbolAddress((void**)&Vh, g_Vh);
    cudaGetSymbolAddress((void**)&Vl, g_Vl);

    cudaFuncSetAttribute(tc_gemm<0>, cudaFuncAttributeMaxDynamicSharedMemorySize, SMEM_GEMM);
    cudaFuncSetAttribute(tc_gemm<1>, cudaFuncAttributeMaxDynamicSharedMemorySize, SMEM_GEMM);
    cudaFuncSetAttribute(flash_attn, cudaFuncAttributeMaxDynamicSharedMemorySize, SMEM_FA);

    const size_t nX4 = (size_t)Mtot * Cc / 4;

    // 1) split x -> bf16 hi/lo ; transpose-split Wqkv ; zero V padding rows
    split_kernel<<<2048, 256>>>(x, xhi, xlo, nX4);
    {
        dim3 g(3 * Cc / 32, Cc / 32), blk(32, 8);
        transpose_split<<<g, blk>>>(Wqkv, w1h, w1l, Cc, 3 * Cc);
    }
    {
        size_t tot = (size_t)BH * (NPAD - Nn) * Dd;
        zero_vpad<<<(int)((tot + 255) / 256), 256>>>(Vh, Vl);
    }
    // 2) qkv GEMM -> split directly into padded Q/K/V hi/lo buffers
    {
        dim3 grid(3 * Cc / 128, Mtot / 128);
        tc_gemm<1><<<grid, 256, SMEM_GEMM>>>(xhi, xlo, w1h, w1l, bqkv, nullptr, 3 * Cc,
                                             Qh, Ql, Kh, Kl, Vh, Vl);
    }
    // 3) flash attention -> writes att split directly into xhi/xlo
    {
        dim3 grid(4, BH);
        flash_attn<<<grid, 128, SMEM_FA>>>(Qh, Ql, Kh, Kl, Vh, Vl, xhi, xlo);
    }
    // 4) depthwise conv on V + residual, re-split in place
    {
        size_t total = (size_t)Bn * (GRID3 * GRID3) * Cc;
        conv_split<<<(int)((total + 255) / 256), 256>>>(Vh, Vl, dwcw, dwcb, xhi, xlo);
    }
    // 5) proj GEMM -> out
    {
        dim3 g(Cc / 32, Cc / 32), blk(32, 8);
        transpose_split<<<g, blk>>>(Wproj, w2h, w2l, Cc, Cc);
        dim3 grid(Cc / 128, Mtot / 128);
        tc_gemm<0><<<grid, 256, SMEM_GEMM>>>(xhi, xlo, w2h, w2l, bproj, out, Cc,
                                             nullptr, nullptr, nullptr, nullptr, nullptr, nullptr);
    }
}

// round 5
// speedup vs baseline: 2.1001x; 1.0364x over previous
#include <cuda_runtime.h>
#include <cuda_bf16.h>
#include <cstdint>

// Problem constants
#define Bn   256
#define Nn   197
#define Cc   768
#define Hh   12
#define Dd   64
#define GRID3 14
#define Mtot (Bn * Nn)          // 50432 = 394 * 128
#define BH   (Bn * Hh)          // 3072
#define NPAD 256                // padded sequence for attention buffers

// ---------------------------------------------------------------------------
// Scratch (device globals: allocation-free, graph-capturable)
// ---------------------------------------------------------------------------
__device__ __align__(128) __nv_bfloat16 g_xhi[(size_t)Mtot * Cc]; // A hi (x, then att)
__device__ __align__(128) __nv_bfloat16 g_xlo[(size_t)Mtot * Cc]; // A lo
__device__ __align__(128) __nv_bfloat16 g_w1h[(size_t)3 * Cc * Cc];
__device__ __align__(128) __nv_bfloat16 g_w1l[(size_t)3 * Cc * Cc];
__device__ __align__(128) __nv_bfloat16 g_w2h[(size_t)Cc * Cc];
__device__ __align__(128) __nv_bfloat16 g_w2l[(size_t)Cc * Cc];
// per-(b,h) padded Q/K/V, hi/lo split: [BH][NPAD][64]
__device__ __align__(128) __nv_bfloat16 g_Qh[(size_t)BH * NPAD * Dd];
__device__ __align__(128) __nv_bfloat16 g_Ql[(size_t)BH * NPAD * Dd];
__device__ __align__(128) __nv_bfloat16 g_Kh[(size_t)BH * NPAD * Dd];
__device__ __align__(128) __nv_bfloat16 g_Kl[(size_t)BH * NPAD * Dd];
__device__ __align__(128) __nv_bfloat16 g_Vh[(size_t)BH * NPAD * Dd];
__device__ __align__(128) __nv_bfloat16 g_Vl[(size_t)BH * NPAD * Dd];

// ---------------------------------------------------------------------------
// Helpers (base-ISA only)
// ---------------------------------------------------------------------------
__device__ __forceinline__ uint32_t smem_u32(const void* p) {
    uint32_t a;
    asm("{ .reg .u64 t; cvta.to.shared.u64 t, %1; cvt.u32.u64 %0, t; }" : "=r"(a) : "l"(p));
    return a;
}
__device__ __forceinline__ void cp16(uint32_t dst, const void* src) {
    asm volatile("cp.async.cg.shared.global [%0], [%1], 16;" :: "r"(dst), "l"(src));
}
__device__ __forceinline__ void ldsm4(uint32_t* r, uint32_t a) {
    asm volatile("ldmatrix.sync.aligned.m8n8.x4.shared.b16 {%0,%1,%2,%3}, [%4];"
        : "=r"(r[0]), "=r"(r[1]), "=r"(r[2]), "=r"(r[3]) : "r"(a));
}
__device__ __forceinline__ void ldsm2(uint32_t* r, uint32_t a) {
    asm volatile("ldmatrix.sync.aligned.m8n8.x2.shared.b16 {%0,%1}, [%2];"
        : "=r"(r[0]), "=r"(r[1]) : "r"(a));
}
__device__ __forceinline__ void ldsm2t(uint32_t* r, uint32_t a) {
    asm volatile("ldmatrix.sync.aligned.m8n8.x2.trans.shared.b16 {%0,%1}, [%2];"
        : "=r"(r[0]), "=r"(r[1]) : "r"(a));
}
__device__ __forceinline__ void mma16816(float* c, const uint32_t* a, const uint32_t* b) {
    asm volatile(
        "mma.sync.aligned.m16n8k16.row.col.f32.bf16.bf16.f32 "
        "{%0,%1,%2,%3}, {%4,%5,%6,%7}, {%8,%9}, {%0,%1,%2,%3};"
        : "+f"(c[0]), "+f"(c[1]), "+f"(c[2]), "+f"(c[3])
        : "r"(a[0]), "r"(a[1]), "r"(a[2]), "r"(a[3]), "r"(b[0]), "r"(b[1]));
}
__device__ __forceinline__ void split2(float x, float y, uint32_t& hi, uint32_t& lo) {
    __nv_bfloat16 hx = __float2bfloat16(x), hy = __float2bfloat16(y);
    __nv_bfloat162 H(hx, hy);
    __nv_bfloat162 L(__float2bfloat16(x - __bfloat162float(hx)),
                     __float2bfloat16(y - __bfloat162float(hy)));
    hi = *reinterpret_cast<uint32_t*>(&H);
    lo = *reinterpret_cast<uint32_t*>(&L);
}

// ---------------------------------------------------------------------------
// Conversion kernels
// ---------------------------------------------------------------------------
__global__ __launch_bounds__(256) void split_kernel(
    const float* __restrict__ in, __nv_bfloat16* __restrict__ hi,
    __nv_bfloat16* __restrict__ lo, size_t n4)
{
    size_t i = (size_t)blockIdx.x * 256 + threadIdx.x;
    size_t stride = (size_t)gridDim.x * 256;
    for (; i < n4; i += stride) {
        float4 v = ((const float4*)in)[i];
        uint32_t h0, l0, h1, l1;
        split2(v.x, v.y, h0, l0);
        split2(v.z, v.w, h1, l1);
        ((uint32_t*)hi)[i * 2 + 0] = h0;
        ((uint32_t*)hi)[i * 2 + 1] = h1;
        ((uint32_t*)lo)[i * 2 + 0] = l0;
        ((uint32_t*)lo)[i * 2 + 1] = l1;
    }
}

// W is (K x N) row-major; emit W^T split as hi/lo [N x K] bf16.
__global__ __launch_bounds__(256) void transpose_split(
    const float* __restrict__ W, __nv_bfloat16* __restrict__ hi,
    __nv_bfloat16* __restrict__ lo, int K, int N)
{
    __shared__ float t[32][33];
    int bx = blockIdx.x * 32, by = blockIdx.y * 32;
    int tx = threadIdx.x, ty = threadIdx.y;
#pragma unroll
    for (int r = 0; r < 32; r += 8)
        t[ty + r][tx] = W[(size_t)(by + ty + r) * N + bx + tx];
    __syncthreads();
#pragma unroll
    for (int r = 0; r < 32; r += 8) {
        float v = t[tx][ty + r];
        __nv_bfloat16 h = __float2bfloat16(v);
        size_t o = (size_t)(bx + ty + r) * K + by + tx;
        hi[o] = h;
        lo[o] = __float2bfloat16(v - __bfloat162float(h));
    }
}

// zero the padding rows (197..255) of V buffers
__global__ __launch_bounds__(256) void zero_vpad(
    __nv_bfloat16* __restrict__ Vh, __nv_bfloat16* __restrict__ Vl)
{
    size_t idx = (size_t)blockIdx.x * 256 + threadIdx.x;
    const size_t total = (size_t)BH * (NPAD - Nn) * Dd;
    if (idx >= total) return;
    int d = idx % Dd;
    size_t t = idx / Dd;
    int r = Nn + (int)(t % (NPAD - Nn));
    int bh = (int)(t / (NPAD - Nn));
    size_t o = ((size_t)bh * NPAD + r) * Dd + d;
    Vh[o] = __float2bfloat16(0.f);
    Vl[o] = __float2bfloat16(0.f);
}

// ---------------------------------------------------------------------------
// HMMA bf16x3 GEMM: C[M,N] = A[M,768]*B[N,768]^T + bias
// 3-stage cp.async pipeline, ONE __syncthreads per chunk.
// MODE 0: write fp32 C. MODE 1 (qkv): split-write into g_Q/K/V hi/lo padded.
// ---------------------------------------------------------------------------
#define KC   64
#define NCH  (Cc / KC)               // 12
#define LDT  72
#define ROWB (LDT * 2)               // 144 B
#define TILE_PB (128 * ROWB)         // 18432
#define STAGE_B (4 * TILE_PB)        // 73728
#define SMEM_GEMM (3 * STAGE_B)      // 221184

template<int MODE>
__global__ __launch_bounds__(256)
void tc_gemm(const __nv_bfloat16* __restrict__ Ahi, const __nv_bfloat16* __restrict__ Alo,
             const __nv_bfloat16* __restrict__ Bhi, const __nv_bfloat16* __restrict__ Blo,
             const float* __restrict__ bias, float* __restrict__ C, int N,
             __nv_bfloat16* Qh, __nv_bfloat16* Ql,
             __nv_bfloat16* Kh, __nv_bfloat16* Kl,
             __nv_bfloat16* Vh, __nv_bfloat16* Vl)
{
    extern __shared__ char smem[];
    const uint32_t sb = smem_u32(smem);
    const int tid = threadIdx.x, lane = tid & 31, wid = tid >> 5;
    const int m0 = blockIdx.y * 128, n0 = blockIdx.x * 128;
    const int wm = wid >> 2, wn = wid & 3;

    const int lrow = tid >> 1;
    const int lc0  = (tid & 1) * 4;
    const __nv_bfloat16* gAh = Ahi + (size_t)(m0 + lrow) * Cc + lc0 * 8;
    const __nv_bfloat16* gAl = Alo + (size_t)(m0 + lrow) * Cc + lc0 * 8;
    const __nv_bfloat16* gBh = Bhi + (size_t)(n0 + lrow) * Cc + lc0 * 8;
    const __nv_bfloat16* gBl = Blo + (size_t)(n0 + lrow) * Cc + lc0 * 8;
    const uint32_t ldst = lrow * ROWB + lc0 * 16;

#define LOADC(c, s) do {                                                \
    uint32_t _d = sb + (s) * STAGE_B + ldst;                            \
    int _k = (c) * KC;                                                  \
    _Pragma("unroll")                                                   \
    for (int q = 0; q < 4; ++q) {                                       \
        cp16(_d + q * 16,               gAh + _k + q * 8);              \
        cp16(_d + TILE_PB + q * 16,     gAl + _k + q * 8);              \
        cp16(_d + 2 * TILE_PB + q * 16, gBh + _k + q * 8);              \
        cp16(_d + 3 * TILE_PB + q * 16, gBl + _k + q * 8);              \
    }                                                                   \
    asm volatile("cp.async.commit_group;" ::: "memory");                \
} while (0)

    float acc[4][4][4];
#pragma unroll
    for (int i = 0; i < 4; i++)
#pragma unroll
        for (int j = 0; j < 4; j++)
#pragma unroll
            for (int k = 0; k < 4; k++) acc[i][j][k] = 0.f;

    LOADC(0, 0);
    LOADC(1, 1);

    const uint32_t aoff = (uint32_t)(wm * 64 + (lane & 15)) * ROWB + ((lane >> 4) << 3) * 2;
    const int lb = lane & 15;
    const uint32_t boff = (uint32_t)(wn * 32 + (lb & 7)) * ROWB + ((lb >> 3) << 3) * 2;

    for (int c = 0; c < NCH; ++c) {
        // wait for chunk c's group (prefetch for c+1 may stay in flight)
        if (c + 1 < NCH) asm volatile("cp.async.wait_group 1;" ::: "memory");
        else             asm volatile("cp.async.wait_group 0;" ::: "memory");
        __syncthreads();   // single barrier per chunk

        // prefetch chunk c+2 into stage (c+2)%3 — disjoint from stage c%3 being read
        if (c + 2 < NCH) LOADC(c + 2, (c + 2) % 3);

        const uint32_t S = sb + (uint32_t)(c % 3) * STAGE_B;
#pragma unroll
        for (int ks = 0; ks < 4; ++ks) {
            uint32_t ah[4][4], al[4][4], bh[4][2], bl[4][2];
#pragma unroll
            for (int im = 0; im < 4; ++im) {
                uint32_t a = S + aoff + (uint32_t)(im * 16) * ROWB + ks * 32;
                ldsm4(ah[im], a);
                ldsm4(al[im], a + TILE_PB);
            }
#pragma unroll
            for (int jn = 0; jn < 4; ++jn) {
                uint32_t a = S + 2 * TILE_PB + boff + (uint32_t)(jn * 8) * ROWB + ks * 32;
                ldsm2(bh[jn], a);
                ldsm2(bl[jn], a + TILE_PB);
            }
#pragma unroll
            for (int im = 0; im < 4; ++im)
#pragma unroll
                for (int jn = 0; jn < 4; ++jn) {
                    mma16816(acc[im][jn], ah[im], bh[jn]);
                    mma16816(acc[im][jn], ah[im], bl[jn]);
                    mma16816(acc[im][jn], al[im], bh[jn]);
                }
        }
    }

    const int g = lane >> 2, tc = (lane & 3) * 2;
    if (MODE == 0) {
#pragma unroll
        for (int im = 0; im < 4; ++im) {
            int row = m0 + wm * 64 + im * 16 + g;
#pragma unroll
            for (int jn = 0; jn < 4; ++jn) {
                int col = n0 + wn * 32 + jn * 8 + tc;
                float b0 = bias[col], b1 = bias[col + 1];
                float2 v0 = make_float2(acc[im][jn][0] + b0, acc[im][jn][1] + b1);
                float2 v1 = make_float2(acc[im][jn][2] + b0, acc[im][jn][3] + b1);
                *(float2*)(C + (size_t)row * N + col)       = v0;
                *(float2*)(C + (size_t)(row + 8) * N + col) = v1;
            }
        }
    } else {
#pragma unroll
        for (int jn = 0; jn < 4; ++jn) {
            int col = n0 + wn * 32 + jn * 8 + tc;
            int t = col / Cc, rem = col - t * Cc;
            int hh = rem >> 6, dd = rem & 63;
            __nv_bfloat16* BHp = (t == 0) ? Qh : (t == 1) ? Kh : Vh;
            __nv_bfloat16* BLp = (t == 0) ? Ql : (t == 1) ? Kl : Vl;
            float b0 = bias[col], b1 = bias[col + 1];
#pragma unroll
            for (int im = 0; im < 4; ++im) {
                int row0 = m0 + wm * 64 + im * 16 + g;
#pragma unroll
                for (int rr = 0; rr < 2; ++rr) {
                    int row = row0 + rr * 8;
                    int bb = row / Nn, nn = row - bb * Nn;
                    size_t o = (((size_t)bb * Hh + hh) * NPAD + nn) * Dd + dd;
                    uint32_t hi, lo;
                    split2(acc[im][jn][rr * 2] + b0, acc[im][jn][rr * 2 + 1] + b1, hi, lo);
                    *(uint32_t*)(BHp + o) = hi;
                    *(uint32_t*)(BLp + o) = lo;
                }
            }
        }
    }
#undef LOADC
}

// ---------------------------------------------------------------------------
// Flash attention on HMMA (unchanged from R4)
// ---------------------------------------------------------------------------
#define FA_QB   9216
#define FA_STG  (4 * FA_QB)
#define SMEM_FA (2 * FA_QB + 2 * FA_STG)  // 92160

__global__ __launch_bounds__(128) void flash_attn(
    const __nv_bfloat16* __restrict__ Qh, const __nv_bfloat16* __restrict__ Ql,
    const __nv_bfloat16* __restrict__ Kh, const __nv_bfloat16* __restrict__ Kl,
    const __nv_bfloat16* __restrict__ Vh, const __nv_bfloat16* __restrict__ Vl,
    __nv_bfloat16* __restrict__ xhi, __nv_bfloat16* __restrict__ xlo)
{
    extern __shared__ char smem[];
    const uint32_t sb = smem_u32(smem);
    const int mt = blockIdx.x, bh = blockIdx.y;
    const int b = bh / Hh, h = bh % Hh;
    const int tid = threadIdx.x, lane = tid & 31, w = tid >> 5;

    const uint32_t SQh = sb, SQl = sb + FA_QB;

    {
        int row = tid >> 1, half = tid & 1;
        size_t gq = ((size_t)bh * NPAD + mt * 64 + row) * Dd + half * 32;
        uint32_t d = SQh + row * ROWB + half * 64;
#pragma unroll
        for (int i = 0; i < 4; ++i) {
            cp16(d + i * 16, Qh + gq + i * 8);
            cp16(d + FA_QB + i * 16, Ql + gq + i * 8);
        }
    }
#define LKV(c, s) do {                                                       \
    int row = tid >> 1, half = tid & 1;                                      \
    size_t gk = ((size_t)bh * NPAD + (c) * 64 + row) * Dd + half * 32;       \
    uint32_t d = sb + 2 * FA_QB + (s) * FA_STG + row * ROWB + half * 64;     \
    _Pragma("unroll")                                                        \
    for (int i = 0; i < 4; ++i) {                                            \
        cp16(d + i * 16,              Kh + gk + i * 8);                      \
        cp16(d + FA_QB + i * 16,      Kl + gk + i * 8);                      \
        cp16(d + 2 * FA_QB + i * 16,  Vh + gk + i * 8);                      \
        cp16(d + 3 * FA_QB + i * 16,  Vl + gk + i * 8);                      \
    }                                                                        \
    asm volatile("cp.async.commit_group;" ::: "memory");                     \
} while (0)

    LKV(0, 0);
    LKV(1, 1);

    const uint32_t aoff = (uint32_t)(w * 16 + (lane & 15)) * ROWB + ((lane >> 4) << 3) * 2;
    const int lb = lane & 15;
    const uint32_t koff = (uint32_t)(lb & 7) * ROWB + ((lb >> 3) << 3) * 2;
    const uint32_t voff = (uint32_t)(lane & 15) * ROWB;

    float oA[8][4];
#pragma unroll
    for (int i = 0; i < 8; i++)
#pragma unroll
        for (int j = 0; j < 4; j++) oA[i][j] = 0.f;
    float mx[2] = {-1e30f, -1e30f}, sum[2] = {0.f, 0.f};
    const int tc = (lane & 3) * 2;

    for (int c = 0; c < 4; ++c) {
        if (c < 3) asm volatile("cp.async.wait_group 1;" ::: "memory");
        else       asm volatile("cp.async.wait_group 0;" ::: "memory");
        __syncthreads();

        const uint32_t SK = sb + 2 * FA_QB + (c & 1) * FA_STG;
        const uint32_t SV = SK + 2 * FA_QB;

        float sA[8][4];
#pragma unroll
        for (int i = 0; i < 8; i++)
#pragma unroll
            for (int j = 0; j < 4; j++) sA[i][j] = 0.f;
#pragma unroll
        for (int kk = 0; kk < 4; ++kk) {
            uint32_t qh4[4], ql4[4];
            ldsm4(qh4, SQh + aoff + kk * 32);
            ldsm4(ql4, SQl + aoff + kk * 32);
#pragma unroll
            for (int nt = 0; nt < 8; ++nt) {
                uint32_t kh2[2], kl2[2];
                uint32_t ka = SK + koff + (uint32_t)(nt * 8) * ROWB + kk * 32;
                ldsm2(kh2, ka);
                ldsm2(kl2, ka + FA_QB);
                mma16816(sA[nt], qh4, kh2);
                mma16816(sA[nt], qh4, kl2);
                mma16816(sA[nt], ql4, kh2);
            }
        }

#pragma unroll
        for (int rt = 0; rt < 2; ++rt) {
            float m = -1e30f;
#pragma unroll
            for (int nt = 0; nt < 8; ++nt) {
                int j = c * 64 + nt * 8 + tc;
                float v0 = (j < Nn)     ? sA[nt][rt * 2]     * 0.125f : -1e30f;
                float v1 = (j + 1 < Nn) ? sA[nt][rt * 2 + 1] * 0.125f : -1e30f;
                sA[nt][rt * 2] = v0;
                sA[nt][rt * 2 + 1] = v1;
                m = fmaxf(m, fmaxf(v0, v1));
            }
            m = fmaxf(m, __shfl_xor_sync(~0u, m, 1));
            m = fmaxf(m, __shfl_xor_sync(~0u, m, 2));
            float mn = fmaxf(mx[rt], m);
            float scl = __expf(mx[rt] - mn);
            mx[rt] = mn;
            float ls = 0.f;
#pragma unroll
            for (int nt = 0; nt < 8; ++nt) {
                float p0 = __expf(sA[nt][rt * 2] - mn);
                float p1 = __expf(sA[nt][rt * 2 + 1] - mn);
                sA[nt][rt * 2] = p0;
                sA[nt][rt * 2 + 1] = p1;
                ls += p0 + p1;
                oA[nt][rt * 2] *= scl;
                oA[nt][rt * 2 + 1] *= scl;
            }
            ls += __shfl_xor_sync(~0u, ls, 1);
            ls += __shfl_xor_sync(~0u, ls, 2);
            sum[rt] = sum[rt] * scl + ls;
        }

#pragma unroll
        for (int kk = 0; kk < 4; ++kk) {
            uint32_t ph[4], pl[4];
            split2(sA[2 * kk][0],     sA[2 * kk][1],     ph[0], pl[0]);
            split2(sA[2 * kk][2],     sA[2 * kk][3],     ph[1], pl[1]);
            split2(sA[2 * kk + 1][0], sA[2 * kk + 1][1], ph[2], pl[2]);
            split2(sA[2 * kk + 1][2], sA[2 * kk + 1][3], ph[3], pl[3]);
#pragma unroll
            for (int nd = 0; nd < 8; ++nd) {
                uint32_t vh2[2], vl2[2];
                uint32_t va = SV + voff + (uint32_t)(kk * 16) * ROWB + nd * 16;
                ldsm2t(vh2, va);
                ldsm2t(vl2, va + FA_QB);
                mma16816(oA[nd], ph, vh2);
                mma16816(oA[nd], ph, vl2);
                mma16816(oA[nd], pl, vh2);
            }
        }
        __syncthreads();
        if (c + 2 < 4) LKV(c + 2, c & 1);
    }

    const float i0 = 1.f / sum[0], i1 = 1.f / sum[1];
    const int g = lane >> 2;
    const int q0 = mt * 64 + w * 16 + g;
    const int dcol = h * Dd + tc;
#pragma unroll
    for (int rr = 0; rr < 2; ++rr) {
        int q = q0 + rr * 8;
        if (q >= Nn) continue;
        float inv = rr ? i1 : i0;
        size_t o = ((size_t)b * Nn + q) * Cc + dcol;
#pragma unroll
        for (int nd = 0; nd < 8; ++nd) {
            uint32_t hi, lo;
            split2(oA[nd][rr * 2] * inv, oA[nd][rr * 2 + 1] * inv, hi, lo);
            *(uint32_t*)(xhi + o + nd * 8) = hi;
            *(uint32_t*)(xlo + o + nd * 8) = lo;
        }
    }
#undef LKV
}

// ---------------------------------------------------------------------------
// Fused depthwise conv + residual, 2 channels per thread (bf16x2 loads)
// ---------------------------------------------------------------------------
__global__ __launch_bounds__(256) void conv_split(
    const __nv_bfloat16* __restrict__ Vh, const __nv_bfloat16* __restrict__ Vl,
    const float* __restrict__ wgt, const float* __restrict__ bias,
    __nv_bfloat16* __restrict__ xhi, __nv_bfloat16* __restrict__ xlo)
{
    size_t idx = (size_t)blockIdx.x * 256 + threadIdx.x;
    const size_t total = (size_t)Bn * (GRID3 * GRID3) * (Cc / 2);
    if (idx >= total) return;

    int c2 = (int)(idx % (Cc / 2));
    int c = c2 * 2;
    size_t t = idx / (Cc / 2);
    int x = (int)(t % GRID3); t /= GRID3;
    int y = (int)(t % GRID3);
    int b = (int)(t / GRID3);

    int hh = c >> 6, dd = c & 63;
    const size_t vb = ((size_t)(b * Hh + hh) * NPAD) * Dd + dd;

    float a0 = bias[c], a1 = bias[c + 1];
#pragma unroll
    for (int dy = -1; dy <= 1; ++dy) {
        int yy = y + dy;
        if (yy < 0 || yy >= GRID3) continue;
#pragma unroll
        for (int dx = -1; dx <= 1; ++dx) {
            int xx = x + dx;
            if (xx < 0 || xx >= GRID3) continue;
            size_t a = vb + (size_t)(1 + yy * GRID3 + xx) * Dd;
            __nv_bfloat162 vh = *(const __nv_bfloat162*)(Vh + a);
            __nv_bfloat162 vl = *(const __nv_bfloat162*)(Vl + a);
            float v0 = __bfloat162float(vh.x) + __bfloat162float(vl.x);
            float v1 = __bfloat162float(vh.y) + __bfloat162float(vl.y);
            int wi = (dy + 1) * 3 + (dx + 1);
            a0 += v0 * wgt[c * 9 + wi];
            a1 += v1 * wgt[(c + 1) * 9 + wi];
        }
    }
    size_t o = ((size_t)b * Nn + 1 + y * GRID3 + x) * Cc + c;
    __nv_bfloat162 xh = *(__nv_bfloat162*)(xhi + o);
    __nv_bfloat162 xl = *(__nv_bfloat162*)(xlo + o);
    float v0 = __bfloat162float(xh.x) + __bfloat162float(xl.x) + a0;
    float v1 = __bfloat162float(xh.y) + __bfloat162float(xl.y) + a1;
    uint32_t hi, lo;
    split2(v0, v1, hi, lo);
    *(uint32_t*)(xhi + o) = hi;
    *(uint32_t*)(xlo + o) = lo;
}

// ---------------------------------------------------------------------------
extern "C" void kernel_launch(void* const* d_in, const int* in_sizes, int n_in,
                              void* d_out, int out_size)
{
    (void)in_sizes; (void)n_in; (void)out_size;
    const float* x     = (const float*)d_in[0];
    const float* Wqkv  = (const float*)d_in[1];
    const float* bqkv  = (const float*)d_in[2];
    const float* Wproj = (const float*)d_in[3];
    const float* bproj = (const float*)d_in[4];
    const float* dwcw  = (const float*)d_in[5];
    const float* dwcb  = (const float*)d_in[6];
    float* out = (float*)d_out;

    __nv_bfloat16 *xhi, *xlo, *w1h, *w1l, *w2h, *w2l;
    __nv_bfloat16 *Qh, *Ql, *Kh, *Kl, *Vh, *Vl;
    cudaGetSymbolAddress((void**)&xhi, g_xhi);
    cudaGetSymbolAddress((void**)&xlo, g_xlo);
    cudaGetSymbolAddress((void**)&w1h, g_w1h);
    cudaGetSymbolAddress((void**)&w1l, g_w1l);
    cudaGetSymbolAddress((void**)&w2h, g_w2h);
    cudaGetSymbolAddress((void**)&w2l, g_w2l);
    cudaGetSymbolAddress((void**)&Qh, g_Qh);
    cudaGetSymbolAddress((void**)&Ql, g_Ql);
    cudaGetSymbolAddress((void**)&Kh, g_Kh);
    cudaGetSymbolAddress((void**)&Kl, g_Kl);
    cudaGetSymbolAddress((void**)&Vh, g_Vh);
    cudaGetSymbolAddress((void**)&Vl, g_Vl);

    cudaFuncSetAttribute(tc_gemm<0>, cudaFuncAttributeMaxDynamicSharedMemorySize, SMEM_GEMM);
    cudaFuncSetAttribute(tc_gemm<1>, cudaFuncAttributeMaxDynamicSharedMemorySize, SMEM_GEMM);
    cudaFuncSetAttribute(flash_attn, cudaFuncAttributeMaxDynamicSharedMemorySize, SMEM_FA);

    const size_t nX4 = (size_t)Mtot * Cc / 4;

    split_kernel<<<2048, 256>>>(x, xhi, xlo, nX4);
    {
        dim3 g(3 * Cc / 32, Cc / 32), blk(32, 8);
        transpose_split<<<g, blk>>>(Wqkv, w1h, w1l, Cc, 3 * Cc);
    }
    {
        size_t tot = (size_t)BH * (NPAD - Nn) * Dd;
        zero_vpad<<<(int)((tot + 255) / 256), 256>>>(Vh, Vl);
    }
    {
        dim3 grid(3 * Cc / 128, Mtot / 128);
        tc_gemm<1><<<grid, 256, SMEM_GEMM>>>(xhi, xlo, w1h, w1l, bqkv, nullptr, 3 * Cc,
                                             Qh, Ql, Kh, Kl, Vh, Vl);
    }
    {
        dim3 grid(4, BH);
        flash_attn<<<grid, 128, SMEM_FA>>>(Qh, Ql, Kh, Kl, Vh, Vl, xhi, xlo);
    }
    {
        size_t total = (size_t)Bn * (GRID3 * GRID3) * (Cc / 2);
        conv_split<<<(int)((total + 255) / 256), 256>>>(Vh, Vl, dwcw, dwcb, xhi, xlo);
    }
    {
        dim3 g(Cc / 32, Cc / 32), blk(32, 8);
        transpose_split<<<g, blk>>>(Wproj, w2h, w2l, Cc, Cc);
        dim3 grid(Cc / 128, Mtot / 128);
        tc_gemm<0><<<grid, 256, SMEM_GEMM>>>(xhi, xlo, w2h, w2l, bproj, out, Cc,
                                             nullptr, nullptr, nullptr, nullptr, nullptr, nullptr);
    }
}